// round 15
// baseline (speedup 1.0000x reference)
#include <cuda_runtime.h>
#include <cstdint>

#define TOK 1024
#define DM  768
#define FF  2048
#define KK  64
#define CAP 262144

#define PACK2(out, lo, hi) asm("mov.b64 %0, {%1, %2};" : "=l"(out) : "r"(__float_as_uint(lo)), "r"(__float_as_uint(hi)))
#define UNPACK2(lo, hi, in) do { unsigned _ul, _uh; asm("mov.b64 {%0, %1}, %2;" : "=r"(_ul), "=r"(_uh) : "l"(in)); lo = __uint_as_float(_ul); hi = __uint_as_float(_uh); } while(0)
#define FMA2(d, a, b, c) asm("fma.rn.f32x2 %0, %1, %2, %3;" : "=l"(d) : "l"(a), "l"(b), "l"(c))

__constant__ int c_pair_up[9]   = {0, 0,1,3, 0,1,2,3,4};
__constant__ int c_pair_base[3] = {0,1,4};
__constant__ int c_npairs[3]    = {1,3,5};
__constant__ int c_pair_down_[9]= {3,4,4,4,5,5,5,5,5};

__device__ float g_WdecT[(size_t)6*FF*DM];
__device__ float g_dotWb[36*FF];
__device__ float g_pre[(size_t)8*TOK*FF];
__device__ float g_contrib[(size_t)9*TOK*FF];
__device__ float g_encval[5*TOK*KK];
__device__ int   g_encidx[5*TOK*KK];
__device__ int   g_segcnt[8*9*FF];
__device__ unsigned g_bits[(size_t)9*8*FF*8];
__device__ int   g_colptr[9*2049];
__device__ int   g_ent_g[(size_t)9*CAP];
__device__ float g_ent_v[(size_t)9*CAP];
__device__ int   g_flags[4];

__global__ void k_mreset(){ if (threadIdx.x < 4) g_flags[threadIdx.x] = 0; }
__global__ void k_mdetect(const unsigned int* __restrict__ m){
    unsigned int w = m[blockIdx.x*256 + threadIdx.x];
    if (w == 0x3F800000u) atomicOr(&g_flags[0], 1);
    else if (w == 0x3F803F80u || w == 0x00003F80u) atomicOr(&g_flags[2], 1);
    else if (w > 1u) atomicOr(&g_flags[1], 1);
}
__global__ void k_mclassify(){
    int dt;
    if (g_flags[2]) dt = 3;
    else if (g_flags[0]) dt = 2;
    else if (g_flags[1]) dt = 0;
    else dt = 1;
    g_flags[3] = dt;
}
__device__ __forceinline__ int mask_at(const void* m, size_t idx, int dt){
    if (dt == 2) return ((const float*)m)[idx] != 0.f;
    if (dt == 1) return ((const int*)m)[idx] != 0;
    if (dt == 0) return ((const unsigned char*)m)[idx] != 0;
    return ((const unsigned short*)m)[idx] != 0;
}

__global__ void k_transpose(const float* __restrict__ Wdec){
    __shared__ float tile[32][33];
    int m = blockIdx.z, f0 = blockIdx.x*32, d0 = blockIdx.y*32;
    int tx = threadIdx.x, ty = threadIdx.y;
    const float* src = Wdec + (size_t)m*DM*FF;
    #pragma unroll
    for (int i=0;i<32;i+=8) tile[ty+i][tx] = src[(size_t)(d0+ty+i)*FF + f0+tx];
    __syncthreads();
    float* dst = g_WdecT + (size_t)m*FF*DM;
    #pragma unroll
    for (int i=0;i<32;i+=8) dst[(size_t)(f0+ty+i)*DM + d0+tx] = tile[tx][ty+i];
}

__global__ __launch_bounds__(256) void k_dotwb(const float* __restrict__ Wenc,
                                               const float* __restrict__ bdec){
    __shared__ float sb[6*DM];
    int tid = threadIdx.x;
    for (int i=tid;i<6*DM;i+=256) sb[i] = bdec[i];
    __syncthreads();
    int a = blockIdx.y;
    int f = blockIdx.x*8 + (tid>>5);
    int lane = tid & 31;
    const float* wr = Wenc + ((size_t)a*FF + f)*DM;
    float acc[6] = {0,0,0,0,0,0};
    for (int i=lane;i<DM;i+=32){
        float w = wr[i];
        #pragma unroll
        for (int b=0;b<6;b++) acc[b] = fmaf(w, sb[b*DM + i], acc[b]);
    }
    #pragma unroll
    for (int b=0;b<6;b++){
        #pragma unroll
        for (int off=16;off;off>>=1) acc[b] += __shfl_down_sync(~0u, acc[b], off);
    }
    if (lane==0){
        #pragma unroll
        for (int b=0;b<6;b++) g_dotWb[(a*6+b)*FF + f] = acc[b];
    }
}

// GEMM: R12-exact layout (measured best). Single tweak: B pairs read directly
// from Bs as ulonglong2 (same 16B loads, removes 4 mov.b64/kk). A keeps PACK2.
__global__ __launch_bounds__(256) void k_gemm(const float* __restrict__ resid,
        const float* __restrict__ ln1, const float* __restrict__ ln2,
        const float* __restrict__ Wenc, const float* __restrict__ benc,
        const float* __restrict__ bdec)
{
    int s = blockIdx.z;
    const float* X;
    if (s >= 5)      X = resid;
    else if (s < 3)  X = ln1 + (size_t)s*TOK*DM;
    else             X = ln2 + (size_t)(s-3)*TOK*DM;
    int m = (s < 5) ? s : (s - 2);
    const float* W = Wenc + (size_t)m*FF*DM;
    float* out = g_pre + (size_t)s*TOK*FF;

    __shared__ __align__(16) float As[2][8][132];
    __shared__ __align__(16) float Bs[2][8][132];
    int tid = threadIdx.x, ty = tid>>4, tx = tid&15;
    int rowA = blockIdx.y*128, colB = blockIdx.x*128;
    unsigned long long acc2[8][4];
    #pragma unroll
    for (int i=0;i<8;i++)
        #pragma unroll
        for (int j=0;j<4;j++) acc2[i][j] = 0ull;
    int lr = tid>>1, lc = (tid&1)*4;
    const float* Aptr = X + (size_t)(rowA+lr)*DM + lc;
    const float* Bptr = W + (size_t)(colB+lr)*DM + lc;
    const float* bdp  = bdec + m*DM + lc;
    bool sub = (s < 5);

    const int NT = DM/8;
    {
        float4 av = *(const float4*)(Aptr);
        float4 bv = *(const float4*)(Bptr);
        if (sub){
            float4 bd = *(const float4*)(bdp);
            av.x -= bd.x; av.y -= bd.y; av.z -= bd.z; av.w -= bd.w;
        }
        As[0][lc+0][lr]=av.x; As[0][lc+1][lr]=av.y; As[0][lc+2][lr]=av.z; As[0][lc+3][lr]=av.w;
        Bs[0][lc+0][lr]=bv.x; Bs[0][lc+1][lr]=bv.y; Bs[0][lc+2][lr]=bv.z; Bs[0][lc+3][lr]=bv.w;
    }
    int cur = 0;
    for (int t=0; t<NT; t++){
        float4 nav, nbv;
        if (t+1 < NT){
            nav = *(const float4*)(Aptr + (t+1)*8);
            nbv = *(const float4*)(Bptr + (t+1)*8);
            if (sub){
                float4 bd = *(const float4*)(bdp + (t+1)*8);
                nav.x -= bd.x; nav.y -= bd.y; nav.z -= bd.z; nav.w -= bd.w;
            }
        }
        __syncthreads();
        #pragma unroll
        for (int kk=0;kk<8;kk++){
            float4 a0 = *(const float4*)&As[cur][kk][ty*8];
            float4 a1 = *(const float4*)&As[cur][kk][ty*8+4];
            const ulonglong2* pb = (const ulonglong2*)&Bs[cur][kk][tx*8];
            ulonglong2 b03 = pb[0], b47 = pb[1];
            float a[8] = {a0.x,a0.y,a0.z,a0.w,a1.x,a1.y,a1.z,a1.w};
            unsigned long long bp[4] = {b03.x, b03.y, b47.x, b47.y};
            #pragma unroll
            for (int i=0;i<8;i++){
                unsigned long long aa;
                PACK2(aa, a[i], a[i]);
                #pragma unroll
                for (int jp=0;jp<4;jp++) FMA2(acc2[i][jp], aa, bp[jp], acc2[i][jp]);
            }
        }
        if (t+1 < NT){
            int nxt = cur ^ 1;
            As[nxt][lc+0][lr]=nav.x; As[nxt][lc+1][lr]=nav.y; As[nxt][lc+2][lr]=nav.z; As[nxt][lc+3][lr]=nav.w;
            Bs[nxt][lc+0][lr]=nbv.x; Bs[nxt][lc+1][lr]=nbv.y; Bs[nxt][lc+2][lr]=nbv.z; Bs[nxt][lc+3][lr]=nbv.w;
            cur = nxt;
        }
    }
    #pragma unroll
    for (int i=0;i<8;i++){
        int r = rowA + ty*8 + i;
        float* op = out + (size_t)r*FF + colB + tx*8;
        #pragma unroll
        for (int jp=0;jp<4;jp++){
            float vlo, vhi;
            UNPACK2(vlo, vhi, acc2[i][jp]);
            if (s < 5){
                vlo = vlo + benc[s*FF + colB + tx*8 + jp*2];
                vhi = vhi + benc[s*FF + colB + tx*8 + jp*2 + 1];
            }
            op[jp*2]   = vlo;
            op[jp*2+1] = vhi;
        }
    }
}

// ---- radix-select top-64 (measured win, unchanged) ----
struct TopSh {
    int hist[256];
    int wsum[8];
    unsigned P;
    int k;
    int cnt, eqn;
    int eqidx[80];
};

__device__ __forceinline__ unsigned fkey_u(float f){
    unsigned u = __float_as_uint(f);
    return u ^ ((u & 0x80000000u) ? 0xFFFFFFFFu : 0x80000000u);
}

__device__ void radix_top64(float v[8], float* selv, int* seli, bool clampv, TopSh* sh){
    int tid = threadIdx.x;
    unsigned key[8];
    #pragma unroll
    for (int q=0;q<8;q++) key[q] = fkey_u(v[q]);
    if (tid==0){ sh->k = KK; sh->P = 0; sh->cnt = 0; sh->eqn = 0; }
    for (int r=0;r<4;r++){
        int shift = 24 - 8*r;
        sh->hist[tid] = 0;
        __syncthreads();
        unsigned P = sh->P;
        #pragma unroll
        for (int q=0;q<8;q++){
            unsigned u = key[q];
            bool part = (r==0) || ((u >> (shift+8)) == P);
            if (part) atomicAdd(&sh->hist[(u>>shift)&255], 1);
        }
        __syncthreads();
        int h = sh->hist[255-tid];
        int lane = tid&31, wid = tid>>5;
        int s = h;
        #pragma unroll
        for (int off=1; off<32; off<<=1){
            int t2 = __shfl_up_sync(~0u, s, off);
            if (lane >= off) s += t2;
        }
        if (lane==31) sh->wsum[wid] = s;
        __syncthreads();
        int add = 0;
        #pragma unroll
        for (int w=0;w<8;w++) add += (w < wid) ? sh->wsum[w] : 0;
        s += add;
        int k = sh->k;
        __syncthreads();
        if (s >= k && (s - h) < k){
            sh->P = (P << 8) | (unsigned)(255 - tid);
            sh->k = k - (s - h);
        }
        __syncthreads();
    }
    unsigned tau = sh->P;
    #pragma unroll
    for (int q=0;q<8;q++){
        unsigned u = key[q];
        int idx = tid + 256*q;
        if (u > tau){
            int p = atomicAdd(&sh->cnt, 1);
            selv[p] = clampv ? fmaxf(v[q], 0.f) : v[q];
            seli[p] = idx;
        } else if (u == tau){
            int p = atomicAdd(&sh->eqn, 1);
            if (p < 80) sh->eqidx[p] = idx;
        }
    }
    __syncthreads();
    if (tid==0){
        int c = sh->cnt;
        int kf = sh->k;
        int n = sh->eqn; if (n > 80) n = 80;
        float tv = __uint_as_float(tau ^ ((tau & 0x80000000u) ? 0x80000000u : 0xFFFFFFFFu));
        if (clampv) tv = fmaxf(tv, 0.f);
        for (int i=0;i<kf;i++){
            int best = 0x7fffffff, bj = 0;
            for (int j=0;j<n;j++) if (sh->eqidx[j] < best){ best = sh->eqidx[j]; bj = j; }
            sh->eqidx[bj] = 0x7fffffff;
            selv[c+i] = tv; seli[c+i] = best;
        }
    }
    __syncthreads();
}

__global__ __launch_bounds__(256) void k_topk_enc(){
    int s = blockIdx.y, t = blockIdx.x;
    const float* row = g_pre + ((size_t)s*TOK + t)*FF;
    int tid = threadIdx.x;
    float v[8];
    #pragma unroll
    for (int q=0;q<8;q++) v[q] = row[tid + 256*q];
    __shared__ TopSh sh;
    radix_top64(v, g_encval + ((size_t)s*TOK+t)*KK, g_encidx + ((size_t)s*TOK+t)*KK,
                true, &sh);
}

__global__ void k_colcount(const void* __restrict__ masks){
    int p = blockIdx.y, seg = blockIdx.z;
    int f = blockIdx.x*256 + threadIdx.x;
    int dt = g_flags[3];
    size_t base = (size_t)p*FF*FF + (size_t)seg*256*FF + f;
    unsigned* bw = g_bits + (((size_t)(p*8 + seg)*FF) + f)*8;
    int c = 0;
    #pragma unroll
    for (int w=0; w<8; w++){
        unsigned word = 0;
        for (int b=0; b<32; b++)
            word |= (unsigned)mask_at(masks, base + (size_t)(w*32+b)*FF, dt) << b;
        bw[w] = word;
        c += __popc(word);
    }
    g_segcnt[(seg*9 + p)*FF + f] = c;
}

__global__ void k_scan(){
    int p = blockIdx.x, tid = threadIdx.x;
    __shared__ int buf[2][FF];
    int i0 = tid, i1 = tid + 1024;
    int c0 = 0, c1 = 0;
    #pragma unroll
    for (int s=0;s<8;s++){ c0 += g_segcnt[(s*9+p)*FF + i0]; c1 += g_segcnt[(s*9+p)*FF + i1]; }
    buf[0][i0] = c0; buf[0][i1] = c1;
    __syncthreads();
    int src = 0;
    for (int off=1; off<FF; off<<=1){
        int v0 = buf[src][i0] + (i0>=off ? buf[src][i0-off] : 0);
        int v1 = buf[src][i1] + (i1>=off ? buf[src][i1-off] : 0);
        buf[1-src][i0] = v0; buf[1-src][i1] = v1;
        __syncthreads();
        src ^= 1;
    }
    g_colptr[p*2049 + i0 + 1] = buf[src][i0];
    g_colptr[p*2049 + i1 + 1] = buf[src][i1];
    if (tid==0) g_colptr[p*2049] = 0;
}

__global__ void k_emit(){
    int p = blockIdx.y;
    int f = blockIdx.x*256 + threadIdx.x;
    int pos = g_colptr[p*2049 + f];
    int lim = g_colptr[p*2049 + f + 1];
    if (lim > CAP) lim = CAP;
    for (int seg=0; seg<8; seg++){
        const unsigned* bw = g_bits + (((size_t)(p*8 + seg)*FF) + f)*8;
        int gbase = seg*256;
        #pragma unroll
        for (int w=0; w<8; w++){
            unsigned word = bw[w];
            while (word){
                int b = __ffs(word) - 1;
                word &= word - 1;
                if (pos < lim) g_ent_g[(size_t)p*CAP + pos] = gbase + w*32 + b;
                pos++;
            }
        }
    }
}

__global__ __launch_bounds__(256) void k_values(const float* __restrict__ Wenc){
    int p = blockIdx.y, f = blockIdx.x;
    int down = c_pair_down_[p], up = c_pair_up[p];
    __shared__ __align__(16) float4 wd4[DM/4];
    int tid = threadIdx.x;
    const float4* src = (const float4*)(g_WdecT + ((size_t)up*FF + f)*DM);
    if (tid < DM/4) wd4[tid] = src[tid];
    __syncthreads();
    int base = g_colptr[p*2049+f], end = g_colptr[p*2049+f+1];
    if (end > CAP) end = CAP;
    int grp = tid>>2, q = tid&3;
    unsigned gm = 0xFu << ((((unsigned)tid & 31u) >> 2) << 2);
    for (int e = base + grp; e < end; e += 64){
        int g = g_ent_g[(size_t)p*CAP + e];
        const float4* we = (const float4*)(Wenc + ((size_t)down*FF + g)*DM);
        float s = 0.f;
        #pragma unroll 8
        for (int i=0;i<48;i++){
            float4 a = we[i*4+q];
            float4 b = wd4[i*4+q];
            s = fmaf(a.x,b.x,s); s = fmaf(a.y,b.y,s);
            s = fmaf(a.z,b.z,s); s = fmaf(a.w,b.w,s);
        }
        s += __shfl_xor_sync(gm, s, 1);
        s += __shfl_xor_sync(gm, s, 2);
        if (q==0) g_ent_v[(size_t)p*CAP + e] = s;
    }
}

__global__ __launch_bounds__(128) void k_contrib(){
    int p = blockIdx.y, t = blockIdx.x;
    int up = c_pair_up[p];
    __shared__ float c[FF];
    __shared__ int sidx[KK]; __shared__ float sval[KK];
    __shared__ int sof[KK];  __shared__ float sov[KK];
    __shared__ int sb0[KK];  __shared__ int se0[KK];
    int tid = threadIdx.x;
    if (tid < KK){
        sidx[tid] = g_encidx[((size_t)up*TOK + t)*KK + tid];
        sval[tid] = g_encval[((size_t)up*TOK + t)*KK + tid];
    }
    for (int i=tid;i<FF;i+=128) c[i] = 0.f;
    __syncthreads();
    if (tid < KK){
        int me = sidx[tid], r = 0;
        #pragma unroll
        for (int i=0;i<KK;i++) r += (sidx[i] < me);
        sof[r] = me; sov[r] = sval[tid];
    }
    __syncthreads();
    if (tid < KK){
        int fc = sof[tid];
        sb0[tid] = g_colptr[p*2049+fc];
        int e = g_colptr[p*2049+fc+1];
        se0[tid] = (e > CAP) ? CAP : e;
    }
    __syncthreads();
    for (int k=0;k<KK;k++){
        float vj = sov[k];
        if (vj != 0.f){
            for (int e=sb0[k]+tid; e<se0[k]; e+=128)
                c[g_ent_g[(size_t)p*CAP+e]] = fmaf(vj, g_ent_v[(size_t)p*CAP+e],
                                                   c[g_ent_g[(size_t)p*CAP+e]]);
        }
        __syncthreads();
    }
    float4* dst = (float4*)(g_contrib + ((size_t)p*TOK + t)*FF);
    const float4* sc = (const float4*)c;
    for (int i=tid;i<FF/4;i+=128) dst[i] = sc[i];
}

__global__ __launch_bounds__(256) void k_apply(const float* __restrict__ ln2s,
        const float* __restrict__ benc, const float* __restrict__ bdec,
        float* __restrict__ out)
{
    int d = blockIdx.y, t = blockIdx.x;
    int down = 3 + d;
    __shared__ TopSh sh;
    __shared__ float selv[KK]; __shared__ int seli[KK];
    __shared__ int sof[KK];  __shared__ float sov[KK];
    int tid = threadIdx.x;
    int pb = c_pair_base[d], np = c_npairs[d];

    const float* pre = g_pre + ((size_t)(5+d)*TOK + t)*FF;
    float v[8];
    #pragma unroll
    for (int q=0;q<8;q++) v[q] = pre[tid + 256*q];

    for (int qq=0;qq<np;qq++){
        int p = pb + qq, up = c_pair_up[p];
        const float* cp = g_contrib + ((size_t)p*TOK + t)*FF;
        const float* wb = g_dotWb + (down*6 + up)*FF;
        #pragma unroll
        for (int q=0;q<8;q++){
            int i = tid + 256*q;
            v[q] = v[q] + (cp[i] + wb[i]);
        }
    }

    float scl = ln2s[d*TOK + t];
    const float* be  = benc + down*FF;
    const float* wbd = g_dotWb + (down*6+down)*FF;
    #pragma unroll
    for (int q=0;q<8;q++){
        int i = tid + 256*q;
        float tv = v[q] / scl;
        tv = tv + be[i];
        tv = tv - wbd[i];
        v[q] = tv;
    }

    radix_top64(v, selv, seli, false, &sh);

    if (tid < KK){
        int me = seli[tid], r = 0;
        #pragma unroll
        for (int i=0;i<KK;i++) r += (seli[i] < me);
        sof[r] = me; sov[r] = selv[tid];
    }
    __syncthreads();

    float r0 = 0.f, r1 = 0.f, r2 = 0.f;
    const float* WT = g_WdecT + (size_t)down*FF*DM;
    for (int k=0;k<KK;k++){
        float vk = sov[k];
        const float* w = WT + (size_t)sof[k]*DM;
        r0 = fmaf(vk, w[tid],       r0);
        r1 = fmaf(vk, w[tid + 256], r1);
        r2 = fmaf(vk, w[tid + 512], r2);
    }
    r0 = r0 + bdec[down*DM + tid];
    r1 = r1 + bdec[down*DM + tid + 256];
    r2 = r2 + bdec[down*DM + tid + 512];
    float* op = out + ((size_t)d*TOK + t)*DM;
    op[tid] = r0; op[tid+256] = r1; op[tid+512] = r2;
}

extern "C" void kernel_launch(void* const* d_in, const int* in_sizes, int n_in,
                              void* d_out, int out_size) {
    const float* resid = (const float*)d_in[0];
    const float* ln1   = (const float*)d_in[1];
    const float* ln2   = (const float*)d_in[2];
    const float* ln2s  = (const float*)d_in[3];
    const float* Wenc  = (const float*)d_in[4];
    const float* benc  = (const float*)d_in[5];
    const float* Wdec  = (const float*)d_in[6];
    const float* bdec  = (const float*)d_in[7];
    const void*  masks = (const void*)d_in[8];
    float* out = (float*)d_out;

    k_mreset<<<1, 32>>>();
    k_mdetect<<<4096, 256>>>((const unsigned int*)masks);
    k_mclassify<<<1, 1>>>();

    k_transpose<<<dim3(FF/32, DM/32, 6), dim3(32,8)>>>(Wdec);
    k_dotwb<<<dim3(FF/8, 6), 256>>>(Wenc, bdec);
    k_gemm<<<dim3(FF/128, TOK/128, 8), 256>>>(resid, ln1, ln2, Wenc, benc, bdec);
    k_topk_enc<<<dim3(TOK, 5), 256>>>();
    k_colcount<<<dim3(FF/256, 9, 8), 256>>>(masks);
    k_scan<<<9, 1024>>>();
    k_emit<<<dim3(FF/256, 9), 256>>>();
    k_values<<<dim3(FF, 9), 256>>>(Wenc);
    k_contrib<<<dim3(TOK, 9), 128>>>();
    k_apply<<<dim3(TOK, 3), 256>>>(ln2s, benc, bdec, out);
}

// round 17
// speedup vs baseline: 1.0235x; 1.0235x over previous
#include <cuda_runtime.h>
#include <cstdint>

#define TOK 1024
#define DM  768
#define FF  2048
#define KK  64
#define CAP 262144

#define GEMM_NB   1024
#define CC_NB     576          // colcount: 8 x 9 x 8
#define DW_NB     1536         // dotwb: 256 x 6
#define FAT_NB    (GEMM_NB + CC_NB + DW_NB)

#define PACK2(out, lo, hi) asm("mov.b64 %0, {%1, %2};" : "=l"(out) : "r"(__float_as_uint(lo)), "r"(__float_as_uint(hi)))
#define UNPACK2(lo, hi, in) do { unsigned _ul, _uh; asm("mov.b64 {%0, %1}, %2;" : "=r"(_ul), "=r"(_uh) : "l"(in)); lo = __uint_as_float(_ul); hi = __uint_as_float(_uh); } while(0)
#define FMA2(d, a, b, c) asm("fma.rn.f32x2 %0, %1, %2, %3;" : "=l"(d) : "l"(a), "l"(b), "l"(c))

__constant__ int c_pair_up[9]   = {0, 0,1,3, 0,1,2,3,4};
__constant__ int c_pair_base[3] = {0,1,4};
__constant__ int c_npairs[3]    = {1,3,5};
__constant__ int c_pair_down_[9]= {3,4,4,4,5,5,5,5,5};

__device__ float g_WdecT[(size_t)6*FF*DM];
__device__ float g_dotWb[36*FF];
__device__ float g_pre[(size_t)8*TOK*FF];
__device__ float g_contrib[(size_t)9*TOK*FF];
__device__ float g_encval[5*TOK*KK];
__device__ int   g_encidx[5*TOK*KK];
__device__ int   g_segcnt[8*9*FF];
__device__ unsigned g_bits[(size_t)9*8*FF*8];
__device__ int   g_colptr[9*2049];
__device__ int   g_ent_g[(size_t)9*CAP];
__device__ float g_ent_v[(size_t)9*CAP];
__device__ int   g_flags[4];

__global__ void k_mreset(){ if (threadIdx.x < 4) g_flags[threadIdx.x] = 0; }
__global__ void k_mdetect(const unsigned int* __restrict__ m){
    unsigned int w = m[blockIdx.x*256 + threadIdx.x];
    if (w == 0x3F800000u) atomicOr(&g_flags[0], 1);
    else if (w == 0x3F803F80u || w == 0x00003F80u) atomicOr(&g_flags[2], 1);
    else if (w > 1u) atomicOr(&g_flags[1], 1);
}
__global__ void k_mclassify(){
    int dt;
    if (g_flags[2]) dt = 3;
    else if (g_flags[0]) dt = 2;
    else if (g_flags[1]) dt = 0;
    else dt = 1;
    g_flags[3] = dt;
}
__device__ __forceinline__ int mask_at(const void* m, size_t idx, int dt){
    if (dt == 2) return ((const float*)m)[idx] != 0.f;
    if (dt == 1) return ((const int*)m)[idx] != 0;
    if (dt == 0) return ((const unsigned char*)m)[idx] != 0;
    return ((const unsigned short*)m)[idx] != 0;
}

__global__ void k_transpose(const float* __restrict__ Wdec){
    __shared__ float tile[32][33];
    int m = blockIdx.z, f0 = blockIdx.x*32, d0 = blockIdx.y*32;
    int tx = threadIdx.x, ty = threadIdx.y;
    const float* src = Wdec + (size_t)m*DM*FF;
    #pragma unroll
    for (int i=0;i<32;i+=8) tile[ty+i][tx] = src[(size_t)(d0+ty+i)*FF + f0+tx];
    __syncthreads();
    float* dst = g_WdecT + (size_t)m*FF*DM;
    #pragma unroll
    for (int i=0;i<32;i+=8) dst[(size_t)(f0+ty+i)*DM + d0+tx] = tile[tx][ty+i];
}

// ---- fat kernel: GEMM blocks + colcount blocks + dotwb blocks ----
// All three paths byte-identical arithmetic to the standalone kernels.
__global__ __launch_bounds__(256) void k_fat(const float* __restrict__ resid,
        const float* __restrict__ ln1, const float* __restrict__ ln2,
        const float* __restrict__ Wenc, const float* __restrict__ benc,
        const float* __restrict__ bdec, const void* __restrict__ masks)
{
    __shared__ __align__(16) unsigned char smraw[6*DM*4];   // 18432B union
    float* smf = (float*)smraw;
    int tid = threadIdx.x;
    int bid = blockIdx.x;

    if (bid >= GEMM_NB + CC_NB){
        // ---- dotwb path ----
        int idx = bid - (GEMM_NB + CC_NB);
        int xi = idx & 255, a = idx >> 8;
        float* sb = smf;
        for (int i=tid;i<6*DM;i+=256) sb[i] = bdec[i];
        __syncthreads();
        int f = xi*8 + (tid>>5);
        int lane = tid & 31;
        const float* wr = Wenc + ((size_t)a*FF + f)*DM;
        float acc[6] = {0,0,0,0,0,0};
        for (int i=lane;i<DM;i+=32){
            float w = wr[i];
            #pragma unroll
            for (int b=0;b<6;b++) acc[b] = fmaf(w, sb[b*DM + i], acc[b]);
        }
        #pragma unroll
        for (int b=0;b<6;b++){
            #pragma unroll
            for (int off=16;off;off>>=1) acc[b] += __shfl_down_sync(~0u, acc[b], off);
        }
        if (lane==0){
            #pragma unroll
            for (int b=0;b<6;b++) g_dotWb[(a*6+b)*FF + f] = acc[b];
        }
        return;
    }

    if (bid >= GEMM_NB){
        // ---- colcount path ----
        int idx = bid - GEMM_NB;
        int fblk = idx & 7, rest = idx >> 3;
        int p = rest % 9, seg = rest / 9;
        int f = fblk*256 + tid;
        int dt = g_flags[3];
        size_t base = (size_t)p*FF*FF + (size_t)seg*256*FF + f;
        unsigned* bw = g_bits + (((size_t)(p*8 + seg)*FF) + f)*8;
        int c = 0;
        #pragma unroll
        for (int w=0; w<8; w++){
            unsigned word = 0;
            for (int b=0; b<32; b++)
                word |= (unsigned)mask_at(masks, base + (size_t)(w*32+b)*FF, dt) << b;
            bw[w] = word;
            c += __popc(word);
        }
        g_segcnt[(seg*9 + p)*FF + f] = c;
        return;
    }

    // ---- GEMM path (R12-exact arithmetic) ----
    #define AS(b,k) (&smf[((b)*8+(k))*132])
    #define BS(b,k) (&smf[2112 + ((b)*8+(k))*132])
    int s = bid >> 7;
    int rem = bid & 127;
    int rowA = (rem >> 4) * 128;
    int colB = (rem & 15) * 128;
    const float* X;
    if (s >= 5)      X = resid;
    else if (s < 3)  X = ln1 + (size_t)s*TOK*DM;
    else             X = ln2 + (size_t)(s-3)*TOK*DM;
    int m = (s < 5) ? s : (s - 2);
    const float* W = Wenc + (size_t)m*FF*DM;
    float* out = g_pre + (size_t)s*TOK*FF;

    int ty = tid>>4, tx = tid&15;
    unsigned long long acc2[8][4];
    #pragma unroll
    for (int i=0;i<8;i++)
        #pragma unroll
        for (int j=0;j<4;j++) acc2[i][j] = 0ull;
    int lr = tid>>1, lc = (tid&1)*4;
    const float* Aptr = X + (size_t)(rowA+lr)*DM + lc;
    const float* Bptr = W + (size_t)(colB+lr)*DM + lc;
    const float* bdp  = bdec + m*DM + lc;
    bool sub = (s < 5);

    const int NT = DM/8;
    {
        float4 av = *(const float4*)(Aptr);
        float4 bv = *(const float4*)(Bptr);
        if (sub){
            float4 bd = *(const float4*)(bdp);
            av.x -= bd.x; av.y -= bd.y; av.z -= bd.z; av.w -= bd.w;
        }
        AS(0,lc+0)[lr]=av.x; AS(0,lc+1)[lr]=av.y; AS(0,lc+2)[lr]=av.z; AS(0,lc+3)[lr]=av.w;
        BS(0,lc+0)[lr]=bv.x; BS(0,lc+1)[lr]=bv.y; BS(0,lc+2)[lr]=bv.z; BS(0,lc+3)[lr]=bv.w;
    }
    int cur = 0;
    for (int t=0; t<NT; t++){
        float4 nav, nbv;
        if (t+1 < NT){
            nav = *(const float4*)(Aptr + (t+1)*8);
            nbv = *(const float4*)(Bptr + (t+1)*8);
            if (sub){
                float4 bd = *(const float4*)(bdp + (t+1)*8);
                nav.x -= bd.x; nav.y -= bd.y; nav.z -= bd.z; nav.w -= bd.w;
            }
        }
        __syncthreads();
        #pragma unroll
        for (int kk=0;kk<8;kk++){
            float4 a0 = *(const float4*)&AS(cur,kk)[ty*8];
            float4 a1 = *(const float4*)&AS(cur,kk)[ty*8+4];
            const ulonglong2* pb = (const ulonglong2*)&BS(cur,kk)[tx*8];
            ulonglong2 b03 = pb[0], b47 = pb[1];
            float a[8] = {a0.x,a0.y,a0.z,a0.w,a1.x,a1.y,a1.z,a1.w};
            unsigned long long bp[4] = {b03.x, b03.y, b47.x, b47.y};
            #pragma unroll
            for (int i=0;i<8;i++){
                unsigned long long aa;
                PACK2(aa, a[i], a[i]);
                #pragma unroll
                for (int jp=0;jp<4;jp++) FMA2(acc2[i][jp], aa, bp[jp], acc2[i][jp]);
            }
        }
        if (t+1 < NT){
            int nxt = cur ^ 1;
            AS(nxt,lc+0)[lr]=nav.x; AS(nxt,lc+1)[lr]=nav.y; AS(nxt,lc+2)[lr]=nav.z; AS(nxt,lc+3)[lr]=nav.w;
            BS(nxt,lc+0)[lr]=nbv.x; BS(nxt,lc+1)[lr]=nbv.y; BS(nxt,lc+2)[lr]=nbv.z; BS(nxt,lc+3)[lr]=nbv.w;
            cur = nxt;
        }
    }
    #pragma unroll
    for (int i=0;i<8;i++){
        int r = rowA + ty*8 + i;
        float* op = out + (size_t)r*FF + colB + tx*8;
        #pragma unroll
        for (int jp=0;jp<4;jp++){
            float vlo, vhi;
            UNPACK2(vlo, vhi, acc2[i][jp]);
            if (s < 5){
                vlo = vlo + benc[s*FF + colB + tx*8 + jp*2];
                vhi = vhi + benc[s*FF + colB + tx*8 + jp*2 + 1];
            }
            op[jp*2]   = vlo;
            op[jp*2+1] = vhi;
        }
    }
    #undef AS
    #undef BS
}

// ---- radix-select top-64 (measured win, unchanged) ----
struct TopSh {
    int hist[256];
    int wsum[8];
    unsigned P;
    int k;
    int cnt, eqn;
    int eqidx[80];
};

__device__ __forceinline__ unsigned fkey_u(float f){
    unsigned u = __float_as_uint(f);
    return u ^ ((u & 0x80000000u) ? 0xFFFFFFFFu : 0x80000000u);
}

__device__ void radix_top64(float v[8], float* selv, int* seli, bool clampv, TopSh* sh){
    int tid = threadIdx.x;
    unsigned key[8];
    #pragma unroll
    for (int q=0;q<8;q++) key[q] = fkey_u(v[q]);
    if (tid==0){ sh->k = KK; sh->P = 0; sh->cnt = 0; sh->eqn = 0; }
    for (int r=0;r<4;r++){
        int shift = 24 - 8*r;
        sh->hist[tid] = 0;
        __syncthreads();
        unsigned P = sh->P;
        #pragma unroll
        for (int q=0;q<8;q++){
            unsigned u = key[q];
            bool part = (r==0) || ((u >> (shift+8)) == P);
            if (part) atomicAdd(&sh->hist[(u>>shift)&255], 1);
        }
        __syncthreads();
        int h = sh->hist[255-tid];
        int lane = tid&31, wid = tid>>5;
        int s = h;
        #pragma unroll
        for (int off=1; off<32; off<<=1){
            int t2 = __shfl_up_sync(~0u, s, off);
            if (lane >= off) s += t2;
        }
        if (lane==31) sh->wsum[wid] = s;
        __syncthreads();
        int add = 0;
        #pragma unroll
        for (int w=0;w<8;w++) add += (w < wid) ? sh->wsum[w] : 0;
        s += add;
        int k = sh->k;
        __syncthreads();
        if (s >= k && (s - h) < k){
            sh->P = (P << 8) | (unsigned)(255 - tid);
            sh->k = k - (s - h);
        }
        __syncthreads();
    }
    unsigned tau = sh->P;
    #pragma unroll
    for (int q=0;q<8;q++){
        unsigned u = key[q];
        int idx = tid + 256*q;
        if (u > tau){
            int p = atomicAdd(&sh->cnt, 1);
            selv[p] = clampv ? fmaxf(v[q], 0.f) : v[q];
            seli[p] = idx;
        } else if (u == tau){
            int p = atomicAdd(&sh->eqn, 1);
            if (p < 80) sh->eqidx[p] = idx;
        }
    }
    __syncthreads();
    if (tid==0){
        int c = sh->cnt;
        int kf = sh->k;
        int n = sh->eqn; if (n > 80) n = 80;
        float tv = __uint_as_float(tau ^ ((tau & 0x80000000u) ? 0x80000000u : 0xFFFFFFFFu));
        if (clampv) tv = fmaxf(tv, 0.f);
        for (int i=0;i<kf;i++){
            int best = 0x7fffffff, bj = 0;
            for (int j=0;j<n;j++) if (sh->eqidx[j] < best){ best = sh->eqidx[j]; bj = j; }
            sh->eqidx[bj] = 0x7fffffff;
            selv[c+i] = tv; seli[c+i] = best;
        }
    }
    __syncthreads();
}

__global__ __launch_bounds__(256) void k_topk_enc(){
    int s = blockIdx.y, t = blockIdx.x;
    const float* row = g_pre + ((size_t)s*TOK + t)*FF;
    int tid = threadIdx.x;
    float v[8];
    #pragma unroll
    for (int q=0;q<8;q++) v[q] = row[tid + 256*q];
    __shared__ TopSh sh;
    radix_top64(v, g_encval + ((size_t)s*TOK+t)*KK, g_encidx + ((size_t)s*TOK+t)*KK,
                true, &sh);
}

__global__ void k_scan(){
    int p = blockIdx.x, tid = threadIdx.x;
    __shared__ int buf[2][FF];
    int i0 = tid, i1 = tid + 1024;
    int c0 = 0, c1 = 0;
    #pragma unroll
    for (int s=0;s<8;s++){ c0 += g_segcnt[(s*9+p)*FF + i0]; c1 += g_segcnt[(s*9+p)*FF + i1]; }
    buf[0][i0] = c0; buf[0][i1] = c1;
    __syncthreads();
    int src = 0;
    for (int off=1; off<FF; off<<=1){
        int v0 = buf[src][i0] + (i0>=off ? buf[src][i0-off] : 0);
        int v1 = buf[src][i1] + (i1>=off ? buf[src][i1-off] : 0);
        buf[1-src][i0] = v0; buf[1-src][i1] = v1;
        __syncthreads();
        src ^= 1;
    }
    g_colptr[p*2049 + i0 + 1] = buf[src][i0];
    g_colptr[p*2049 + i1 + 1] = buf[src][i1];
    if (tid==0) g_colptr[p*2049] = 0;
}

__global__ void k_emit(){
    int p = blockIdx.y;
    int f = blockIdx.x*256 + threadIdx.x;
    int pos = g_colptr[p*2049 + f];
    int lim = g_colptr[p*2049 + f + 1];
    if (lim > CAP) lim = CAP;
    for (int seg=0; seg<8; seg++){
        const unsigned* bw = g_bits + (((size_t)(p*8 + seg)*FF) + f)*8;
        int gbase = seg*256;
        #pragma unroll
        for (int w=0; w<8; w++){
            unsigned word = bw[w];
            while (word){
                int b = __ffs(word) - 1;
                word &= word - 1;
                if (pos < lim) g_ent_g[(size_t)p*CAP + pos] = gbase + w*32 + b;
                pos++;
            }
        }
    }
}

__global__ __launch_bounds__(256) void k_values(const float* __restrict__ Wenc){
    int p = blockIdx.y, f = blockIdx.x;
    int down = c_pair_down_[p], up = c_pair_up[p];
    __shared__ __align__(16) float4 wd4[DM/4];
    int tid = threadIdx.x;
    const float4* src = (const float4*)(g_WdecT + ((size_t)up*FF + f)*DM);
    if (tid < DM/4) wd4[tid] = src[tid];
    __syncthreads();
    int base = g_colptr[p*2049+f], end = g_colptr[p*2049+f+1];
    if (end > CAP) end = CAP;
    int grp = tid>>2, q = tid&3;
    unsigned gm = 0xFu << ((((unsigned)tid & 31u) >> 2) << 2);
    for (int e = base + grp; e < end; e += 64){
        int g = g_ent_g[(size_t)p*CAP + e];
        const float4* we = (const float4*)(Wenc + ((size_t)down*FF + g)*DM);
        float s = 0.f;
        #pragma unroll 8
        for (int i=0;i<48;i++){
            float4 a = we[i*4+q];
            float4 b = wd4[i*4+q];
            s = fmaf(a.x,b.x,s); s = fmaf(a.y,b.y,s);
            s = fmaf(a.z,b.z,s); s = fmaf(a.w,b.w,s);
        }
        s += __shfl_xor_sync(gm, s, 1);
        s += __shfl_xor_sync(gm, s, 2);
        if (q==0) g_ent_v[(size_t)p*CAP + e] = s;
    }
}

__global__ __launch_bounds__(128) void k_contrib(){
    int p = blockIdx.y, t = blockIdx.x;
    int up = c_pair_up[p];
    __shared__ float c[FF];
    __shared__ int sidx[KK]; __shared__ float sval[KK];
    __shared__ int sof[KK];  __shared__ float sov[KK];
    __shared__ int sb0[KK];  __shared__ int se0[KK];
    int tid = threadIdx.x;
    if (tid < KK){
        sidx[tid] = g_encidx[((size_t)up*TOK + t)*KK + tid];
        sval[tid] = g_encval[((size_t)up*TOK + t)*KK + tid];
    }
    for (int i=tid;i<FF;i+=128) c[i] = 0.f;
    __syncthreads();
    if (tid < KK){
        int me = sidx[tid], r = 0;
        #pragma unroll
        for (int i=0;i<KK;i++) r += (sidx[i] < me);
        sof[r] = me; sov[r] = sval[tid];
    }
    __syncthreads();
    if (tid < KK){
        int fc = sof[tid];
        sb0[tid] = g_colptr[p*2049+fc];
        int e = g_colptr[p*2049+fc+1];
        se0[tid] = (e > CAP) ? CAP : e;
    }
    __syncthreads();
    for (int k=0;k<KK;k++){
        float vj = sov[k];
        if (vj != 0.f){
            for (int e=sb0[k]+tid; e<se0[k]; e+=128)
                c[g_ent_g[(size_t)p*CAP+e]] = fmaf(vj, g_ent_v[(size_t)p*CAP+e],
                                                   c[g_ent_g[(size_t)p*CAP+e]]);
        }
        __syncthreads();
    }
    float4* dst = (float4*)(g_contrib + ((size_t)p*TOK + t)*FF);
    const float4* sc = (const float4*)c;
    for (int i=tid;i<FF/4;i+=128) dst[i] = sc[i];
}

__global__ __launch_bounds__(256) void k_apply(const float* __restrict__ ln2s,
        const float* __restrict__ benc, const float* __restrict__ bdec,
        float* __restrict__ out)
{
    int d = blockIdx.y, t = blockIdx.x;
    int down = 3 + d;
    __shared__ TopSh sh;
    __shared__ float selv[KK]; __shared__ int seli[KK];
    __shared__ int sof[KK];  __shared__ float sov[KK];
    int tid = threadIdx.x;
    int pb = c_pair_base[d], np = c_npairs[d];

    const float* pre = g_pre + ((size_t)(5+d)*TOK + t)*FF;
    float v[8];
    #pragma unroll
    for (int q=0;q<8;q++) v[q] = pre[tid + 256*q];

    for (int qq=0;qq<np;qq++){
        int p = pb + qq, up = c_pair_up[p];
        const float* cp = g_contrib + ((size_t)p*TOK + t)*FF;
        const float* wb = g_dotWb + (down*6 + up)*FF;
        #pragma unroll
        for (int q=0;q<8;q++){
            int i = tid + 256*q;
            v[q] = v[q] + (cp[i] + wb[i]);
        }
    }

    float scl = ln2s[d*TOK + t];
    const float* be  = benc + down*FF;
    const float* wbd = g_dotWb + (down*6+down)*FF;
    #pragma unroll
    for (int q=0;q<8;q++){
        int i = tid + 256*q;
        float tv = v[q] / scl;
        tv = tv + be[i];
        tv = tv - wbd[i];
        v[q] = tv;
    }

    radix_top64(v, selv, seli, false, &sh);

    if (tid < KK){
        int me = seli[tid], r = 0;
        #pragma unroll
        for (int i=0;i<KK;i++) r += (seli[i] < me);
        sof[r] = me; sov[r] = selv[tid];
    }
    __syncthreads();

    float r0 = 0.f, r1 = 0.f, r2 = 0.f;
    const float* WT = g_WdecT + (size_t)down*FF*DM;
    for (int k=0;k<KK;k++){
        float vk = sov[k];
        const float* w = WT + (size_t)sof[k]*DM;
        r0 = fmaf(vk, w[tid],       r0);
        r1 = fmaf(vk, w[tid + 256], r1);
        r2 = fmaf(vk, w[tid + 512], r2);
    }
    r0 = r0 + bdec[down*DM + tid];
    r1 = r1 + bdec[down*DM + tid + 256];
    r2 = r2 + bdec[down*DM + tid + 512];
    float* op = out + ((size_t)d*TOK + t)*DM;
    op[tid] = r0; op[tid+256] = r1; op[tid+512] = r2;
}

extern "C" void kernel_launch(void* const* d_in, const int* in_sizes, int n_in,
                              void* d_out, int out_size) {
    const float* resid = (const float*)d_in[0];
    const float* ln1   = (const float*)d_in[1];
    const float* ln2   = (const float*)d_in[2];
    const float* ln2s  = (const float*)d_in[3];
    const float* Wenc  = (const float*)d_in[4];
    const float* benc  = (const float*)d_in[5];
    const float* Wdec  = (const float*)d_in[6];
    const float* bdec  = (const float*)d_in[7];
    const void*  masks = (const void*)d_in[8];
    float* out = (float*)d_out;

    k_mreset<<<1, 32>>>();
    k_mdetect<<<4096, 256>>>((const unsigned int*)masks);
    k_mclassify<<<1, 1>>>();

    k_transpose<<<dim3(FF/32, DM/32, 6), dim3(32,8)>>>(Wdec);
    k_fat<<<FAT_NB, 256>>>(resid, ln1, ln2, Wenc, benc, bdec, masks);
    k_topk_enc<<<dim3(TOK, 5), 256>>>();
    k_scan<<<9, 1024>>>();
    k_emit<<<dim3(FF/256, 9), 256>>>();
    k_values<<<dim3(FF, 9), 256>>>(Wenc);
    k_contrib<<<dim3(TOK, 9), 128>>>();
    k_apply<<<dim3(TOK, 3), 256>>>(ln2s, benc, bdec, out);
}